// round 1
// baseline (speedup 1.0000x reference)
#include <cuda_runtime.h>

#define Bn 16
#define Vn 40000
#define Cn 128
#define Hn 56
#define Wn 56
#define En 120000
#define Mn (Bn*Vn)          // 640000
#define HWn (Hn*Wn)         // 3136
#define GBM 64

// ---------------- device scratch (static, no runtime alloc) ----------------
__device__ float g_imgT[(size_t)Bn*HWn*Cn];     // [B,H,W,C]
__device__ float g_A [81920000];                // G, later reused as U
__device__ float g_Dk[81920000];                // d (kept for final sum)
__device__ float g_T0[81920000];                // X@W0+b0 scratch
__device__ float g_T1[81920000];                // X@W1 scratch

__device__ int g_deg[Vn];
__device__ int g_cursor[Vn];
__device__ int g_rowptr[Vn+1];
__device__ int g_col[2*En];

// ---------------- CSR build ----------------
__global__ void zero_csr() {
    int i = blockIdx.x*blockDim.x + threadIdx.x;
    if (i < Vn) { g_deg[i] = 0; g_cursor[i] = 0; }
}

__global__ void count_edges(const int* __restrict__ edges) {
    int e = blockIdx.x*blockDim.x + threadIdx.x;
    if (e < En) {
        atomicAdd(&g_deg[edges[2*e+0]], 1);
        atomicAdd(&g_deg[edges[2*e+1]], 1);
    }
}

__global__ void scan_kernel() {
    __shared__ int partial[1024];
    int t = threadIdx.x;
    const int CH = (Vn + 1023) / 1024;   // 40
    int base = t * CH;
    int s = 0;
    for (int i = 0; i < CH; i++) {
        int idx = base + i;
        if (idx < Vn) s += g_deg[idx];
    }
    partial[t] = s;
    __syncthreads();
    for (int off = 1; off < 1024; off <<= 1) {
        int v = 0;
        if (t >= off) v = partial[t - off];
        __syncthreads();
        partial[t] += v;
        __syncthreads();
    }
    int run = (t == 0) ? 0 : partial[t-1];
    for (int i = 0; i < CH; i++) {
        int idx = base + i;
        if (idx < Vn) { g_rowptr[idx] = run; run += g_deg[idx]; }
    }
    if (t == 1023) g_rowptr[Vn] = run;
}

__global__ void fill_edges(const int* __restrict__ edges) {
    int e = blockIdx.x*blockDim.x + threadIdx.x;
    if (e < En) {
        int i = edges[2*e+0], j = edges[2*e+1];
        int p = atomicAdd(&g_cursor[i], 1);
        g_col[g_rowptr[i] + p] = j;
        int q = atomicAdd(&g_cursor[j], 1);
        g_col[g_rowptr[j] + q] = i;
    }
}

// ---------------- image transpose [B,C,H,W] -> [B,H,W,C] ----------------
__global__ void transpose_img(const float* __restrict__ img) {
    __shared__ float tile[32][33];
    int b   = blockIdx.z;
    int hw0 = blockIdx.x * 32;
    int c0  = blockIdx.y * 32;
    int tx = threadIdx.x, ty = threadIdx.y;
    int hw = hw0 + tx, c = c0 + ty;
    if (hw < HWn)
        tile[ty][tx] = img[((size_t)(b*Cn + c))*HWn + hw];
    __syncthreads();
    int hw2 = hw0 + ty, c2 = c0 + tx;
    if (hw2 < HWn)
        g_imgT[((size_t)(b*HWn + hw2))*Cn + c2] = tile[tx][ty];
}

// ---------------- vert_align + add padded -> g_A ----------------
__global__ void vert_align_kernel(const float* __restrict__ vpos,
                                  const float* __restrict__ vpad) {
    int gw   = (blockIdx.x*blockDim.x + threadIdx.x) >> 5;
    int lane = threadIdx.x & 31;
    if (gw >= Mn) return;
    int b = gw / Vn;

    float px = vpos[(size_t)gw*3 + 0];
    float py = vpos[(size_t)gw*3 + 1];
    float x = (px + 1.0f) * 0.5f * (float)(Wn - 1);
    float y = (py + 1.0f) * 0.5f * (float)(Hn - 1);
    float x0f = floorf(x), y0f = floorf(y);
    float wx1 = x - x0f, wx0 = 1.0f - wx1;
    float wy1 = y - y0f, wy0 = 1.0f - wy1;
    int x0 = (int)x0f, y0 = (int)y0f;

    float4 acc = ((const float4*)(vpad + (size_t)gw*Cn))[lane];

    int   xs_[4] = { x0, x0+1, x0,   x0+1 };
    int   ys_[4] = { y0, y0,   y0+1, y0+1 };
    float ws_[4] = { wx0*wy0, wx1*wy0, wx0*wy1, wx1*wy1 };

    #pragma unroll
    for (int t = 0; t < 4; t++) {
        int xi = xs_[t], yi = ys_[t];
        bool inb = (xi >= 0) && (xi < Wn) && (yi >= 0) && (yi < Hn);
        float wgt = inb ? ws_[t] : 0.0f;
        if (wgt != 0.0f) {
            float4 f = ((const float4*)(g_imgT + ((size_t)((b*Hn + yi)*Wn + xi))*Cn))[lane];
            acc.x += wgt*f.x; acc.y += wgt*f.y; acc.z += wgt*f.z; acc.w += wgt*f.w;
        }
    }
    ((float4*)(g_A + (size_t)gw*Cn))[lane] = acc;
}

// ---------------- fused dual GEMM: Y0 = X@W0+b0, Y1 = X@W1 ----------------
// Both 128x128 weights resident in smem; persistent CTAs stream row tiles.
__global__ void __launch_bounds__(512, 1)
gemm_dual(const float* __restrict__ X,
          const float* __restrict__ W0, const float* __restrict__ bias0,
          const float* __restrict__ W1,
          float* __restrict__ Y0, float* __restrict__ Y1) {
    extern __shared__ float sm[];
    float* sW0 = sm;                    // 128*128
    float* sW1 = sm + Cn*Cn;            // 128*128
    float* sX  = sm + 2*Cn*Cn;          // GBM*128

    int tid = threadIdx.x;
    for (int i = tid; i < Cn*Cn; i += 512) { sW0[i] = W0[i]; sW1[i] = W1[i]; }

    int rg = tid >> 4;      // 0..31  (2 rows each)
    int cg = tid & 15;      // 0..15  (8 cols each)

    float bias[8];
    #pragma unroll
    for (int i = 0; i < 8; i++) bias[i] = bias0[cg*8 + i];
    __syncthreads();

    for (int m0 = blockIdx.x*GBM; m0 < Mn; m0 += gridDim.x*GBM) {
        __syncthreads();
        const float4* Xg  = (const float4*)(X + (size_t)m0*Cn);
        float4*       sX4 = (float4*)sX;
        #pragma unroll
        for (int i = tid; i < GBM*32; i += 512) sX4[i] = Xg[i];
        __syncthreads();

        float a0[2][8], a1[2][8];
        #pragma unroll
        for (int r = 0; r < 2; r++)
            #pragma unroll
            for (int i = 0; i < 8; i++) { a0[r][i] = bias[i]; a1[r][i] = 0.0f; }

        const float* xrow0 = sX + (rg*2)*Cn;
        const float* xrow1 = xrow0 + Cn;

        #pragma unroll 16
        for (int k = 0; k < Cn; k++) {
            float x0 = xrow0[k];
            float x1 = xrow1[k];
            float w0v[8], w1v[8];
            *(float4*)&w0v[0] = *(const float4*)(sW0 + k*Cn + cg*8);
            *(float4*)&w0v[4] = *(const float4*)(sW0 + k*Cn + cg*8 + 4);
            *(float4*)&w1v[0] = *(const float4*)(sW1 + k*Cn + cg*8);
            *(float4*)&w1v[4] = *(const float4*)(sW1 + k*Cn + cg*8 + 4);
            #pragma unroll
            for (int i = 0; i < 8; i++) {
                a0[0][i] += x0 * w0v[i];
                a0[1][i] += x1 * w0v[i];
                a1[0][i] += x0 * w1v[i];
                a1[1][i] += x1 * w1v[i];
            }
        }

        #pragma unroll
        for (int r = 0; r < 2; r++) {
            size_t off = (size_t)(m0 + rg*2 + r)*Cn + cg*8;
            ((float4*)(Y0 + off))[0] = make_float4(a0[r][0], a0[r][1], a0[r][2], a0[r][3]);
            ((float4*)(Y0 + off))[1] = make_float4(a0[r][4], a0[r][5], a0[r][6], a0[r][7]);
            ((float4*)(Y1 + off))[0] = make_float4(a1[r][0], a1[r][1], a1[r][2], a1[r][3]);
            ((float4*)(Y1 + off))[1] = make_float4(a1[r][4], a1[r][5], a1[r][6], a1[r][7]);
        }
    }
}

// ---------------- combine: out = T0 (+Dadd) + sum_{j in N(v)} T1[b,j] ----------------
__global__ void combine_kernel(const float* __restrict__ T0,
                               const float* __restrict__ T1,
                               const float* __restrict__ Dadd,
                               float* __restrict__ outp) {
    int gw   = (blockIdx.x*blockDim.x + threadIdx.x) >> 5;
    int lane = threadIdx.x & 31;
    if (gw >= Mn) return;
    int b = gw / Vn;
    int v = gw - b*Vn;

    size_t off = (size_t)gw*Cn + lane*4;
    float4 acc = *(const float4*)(T0 + off);
    if (Dadd) {
        float4 d = *(const float4*)(Dadd + off);
        acc.x += d.x; acc.y += d.y; acc.z += d.z; acc.w += d.w;
    }
    int s = g_rowptr[v];
    int e = g_rowptr[v+1];
    const float* baseT1 = T1 + (size_t)b*Vn*Cn + lane*4;
    for (int p = s; p < e; p++) {
        int j = __ldg(&g_col[p]);
        float4 t = *(const float4*)(baseT1 + (size_t)j*Cn);
        acc.x += t.x; acc.y += t.y; acc.z += t.z; acc.w += t.w;
    }
    *(float4*)(outp + off) = acc;
}

// ---------------- launch ----------------
extern "C" void kernel_launch(void* const* d_in, const int* in_sizes, int n_in,
                              void* d_out, int out_size) {
    const float* img  = (const float*)d_in[0];
    const float* vpos = (const float*)d_in[1];
    const float* vpad = (const float*)d_in[2];
    const int*   edges= (const int*)  d_in[3];
    const float* w0_1 = (const float*)d_in[4];
    const float* b0_1 = (const float*)d_in[5];
    const float* w1_1 = (const float*)d_in[6];
    const float* w0_2 = (const float*)d_in[7];
    const float* b0_2 = (const float*)d_in[8];
    const float* w1_2 = (const float*)d_in[9];
    const float* w0_3 = (const float*)d_in[10];
    const float* b0_3 = (const float*)d_in[11];
    const float* w1_3 = (const float*)d_in[12];
    float* out = (float*)d_out;

    float *pA, *pD, *pT0, *pT1;
    cudaGetSymbolAddress((void**)&pA,  g_A);
    cudaGetSymbolAddress((void**)&pD,  g_Dk);
    cudaGetSymbolAddress((void**)&pT0, g_T0);
    cudaGetSymbolAddress((void**)&pT1, g_T1);

    const size_t smem = (size_t)(2*Cn*Cn + GBM*Cn) * sizeof(float); // 160 KB
    cudaFuncSetAttribute(gemm_dual, cudaFuncAttributeMaxDynamicSharedMemorySize, (int)smem);

    int nsm = 148;
    cudaDeviceGetAttribute(&nsm, cudaDevAttrMultiProcessorCount, 0);

    // CSR build
    zero_csr<<<(Vn+255)/256, 256>>>();
    count_edges<<<(En+255)/256, 256>>>(edges);
    scan_kernel<<<1, 1024>>>();
    fill_edges<<<(En+255)/256, 256>>>(edges);

    // vert_align
    transpose_img<<<dim3((HWn+31)/32, Cn/32, Bn), dim3(32,32)>>>(img);
    vert_align_kernel<<<Mn/8, 256>>>(vpos, vpad);   // g_A = G

    // conv1: D = G@W0+b0 + A@(G@W1)
    gemm_dual<<<nsm, 512, smem>>>(pA, w0_1, b0_1, w1_1, pT0, pT1);
    combine_kernel<<<Mn/8, 256>>>(pT0, pT1, nullptr, pD);

    // conv2: U = D@W0+b0 + A@(D@W1)   (U stored in g_A)
    gemm_dual<<<nsm, 512, smem>>>(pD, w0_2, b0_2, w1_2, pT0, pT1);
    combine_kernel<<<Mn/8, 256>>>(pT0, pT1, nullptr, pA);

    // conv3 + final add: out = D + (U@W0+b0 + A@(U@W1))
    gemm_dual<<<nsm, 512, smem>>>(pA, w0_3, b0_3, w1_3, pT0, pT1);
    combine_kernel<<<Mn/8, 256>>>(pT0, pT1, pD, out);
}

// round 3
// speedup vs baseline: 4.7666x; 4.7666x over previous
#include <cuda_runtime.h>
#include <cstdint>

#define Bn 16
#define Vn 40000
#define Cn 128
#define Hn 56
#define Wn 56
#define En 120000
#define Mn (Bn*Vn)          // 640000
#define HWn (Hn*Wn)         // 3136

// ---------------- device scratch (static, no runtime alloc) ----------------
__device__ float g_imgT[(size_t)Bn*HWn*Cn];     // [B,H,W,C]
__device__ float g_A [81920000];                // G, later reused as U (tf32-rounded)
__device__ float g_Dk[81920000];                // D (tf32-rounded; residual)
__device__ float g_T0[81920000];                // X@W0+b0
__device__ float g_T1[81920000];                // X@W1
__device__ float g_Bt[6*128*128];               // transposed tf32 weights [n][k]

__device__ int g_deg[Vn];
__device__ int g_cursor[Vn];
__device__ int g_rowptr[Vn+1];
__device__ int g_col[2*En];

// ---------------- helpers ----------------
__device__ __forceinline__ float rnd_tf32(float x) {
    float r;
    asm("cvt.rna.tf32.f32 %0, %1;" : "=f"(r) : "f"(x));
    return r;
}

__device__ __forceinline__ uint32_t smem_u32(const void* p) {
    uint32_t a;
    asm("{ .reg .u64 t; cvta.to.shared.u64 t, %1; cvt.u32.u64 %0, t; }" : "=r"(a) : "l"(p));
    return a;
}

__device__ __forceinline__ void mma_tf32(float* c, const uint32_t* a, const uint32_t* b) {
    asm volatile(
        "mma.sync.aligned.m16n8k8.row.col.f32.tf32.tf32.f32 "
        "{%0,%1,%2,%3}, {%4,%5,%6,%7}, {%8,%9}, {%0,%1,%2,%3};"
        : "+f"(c[0]), "+f"(c[1]), "+f"(c[2]), "+f"(c[3])
        : "r"(a[0]), "r"(a[1]), "r"(a[2]), "r"(a[3]), "r"(b[0]), "r"(b[1]));
}

// ---------------- CSR build ----------------
__global__ void zero_csr() {
    int i = blockIdx.x*blockDim.x + threadIdx.x;
    if (i < Vn) { g_deg[i] = 0; g_cursor[i] = 0; }
}

__global__ void count_edges(const int* __restrict__ edges) {
    int e = blockIdx.x*blockDim.x + threadIdx.x;
    if (e < En) {
        atomicAdd(&g_deg[edges[2*e+0]], 1);
        atomicAdd(&g_deg[edges[2*e+1]], 1);
    }
}

__global__ void scan_kernel() {
    __shared__ int partial[1024];
    int t = threadIdx.x;
    const int CH = (Vn + 1023) / 1024;
    int base = t * CH;
    int s = 0;
    for (int i = 0; i < CH; i++) {
        int idx = base + i;
        if (idx < Vn) s += g_deg[idx];
    }
    partial[t] = s;
    __syncthreads();
    for (int off = 1; off < 1024; off <<= 1) {
        int v = 0;
        if (t >= off) v = partial[t - off];
        __syncthreads();
        partial[t] += v;
        __syncthreads();
    }
    int run = (t == 0) ? 0 : partial[t-1];
    for (int i = 0; i < CH; i++) {
        int idx = base + i;
        if (idx < Vn) { g_rowptr[idx] = run; run += g_deg[idx]; }
    }
    if (t == 1023) g_rowptr[Vn] = run;
}

__global__ void fill_edges(const int* __restrict__ edges) {
    int e = blockIdx.x*blockDim.x + threadIdx.x;
    if (e < En) {
        int i = edges[2*e+0], j = edges[2*e+1];
        int p = atomicAdd(&g_cursor[i], 1);
        g_col[g_rowptr[i] + p] = j;
        int q = atomicAdd(&g_cursor[j], 1);
        g_col[g_rowptr[j] + q] = i;
    }
}

// ---------------- weight prep: Bt[n*128+k] = round_tf32(W[k*128+n]) ----------------
__global__ void prep_weights(const float* __restrict__ W, float* __restrict__ Bt) {
    int i = blockIdx.x*blockDim.x + threadIdx.x;   // 16384
    int n = i >> 7, k = i & 127;
    Bt[i] = rnd_tf32(W[k*128 + n]);
}

// ---------------- image transpose [B,C,H,W] -> [B,H,W,C] ----------------
__global__ void transpose_img(const float* __restrict__ img) {
    __shared__ float tile[32][33];
    int b   = blockIdx.z;
    int hw0 = blockIdx.x * 32;
    int c0  = blockIdx.y * 32;
    int tx = threadIdx.x, ty = threadIdx.y;
    int hw = hw0 + tx, c = c0 + ty;
    if (hw < HWn)
        tile[ty][tx] = img[((size_t)(b*Cn + c))*HWn + hw];
    __syncthreads();
    int hw2 = hw0 + ty, c2 = c0 + tx;
    if (hw2 < HWn)
        g_imgT[((size_t)(b*HWn + hw2))*Cn + c2] = tile[tx][ty];
}

// ---------------- vert_align + add padded -> g_A (tf32-rounded) ----------------
__global__ void vert_align_kernel(const float* __restrict__ vpos,
                                  const float* __restrict__ vpad) {
    int gw   = (blockIdx.x*blockDim.x + threadIdx.x) >> 5;
    int lane = threadIdx.x & 31;
    if (gw >= Mn) return;
    int b = gw / Vn;

    float px = vpos[(size_t)gw*3 + 0];
    float py = vpos[(size_t)gw*3 + 1];
    float x = (px + 1.0f) * 0.5f * (float)(Wn - 1);
    float y = (py + 1.0f) * 0.5f * (float)(Hn - 1);
    float x0f = floorf(x), y0f = floorf(y);
    float wx1 = x - x0f, wx0 = 1.0f - wx1;
    float wy1 = y - y0f, wy0 = 1.0f - wy1;
    int x0 = (int)x0f, y0 = (int)y0f;

    float4 acc = ((const float4*)(vpad + (size_t)gw*Cn))[lane];

    int   xs_[4] = { x0, x0+1, x0,   x0+1 };
    int   ys_[4] = { y0, y0,   y0+1, y0+1 };
    float ws_[4] = { wx0*wy0, wx1*wy0, wx0*wy1, wx1*wy1 };

    #pragma unroll
    for (int t = 0; t < 4; t++) {
        int xi = xs_[t], yi = ys_[t];
        bool inb = (xi >= 0) && (xi < Wn) && (yi >= 0) && (yi < Hn);
        float wgt = inb ? ws_[t] : 0.0f;
        if (wgt != 0.0f) {
            float4 f = ((const float4*)(g_imgT + ((size_t)((b*Hn + yi)*Wn + xi))*Cn))[lane];
            acc.x += wgt*f.x; acc.y += wgt*f.y; acc.z += wgt*f.z; acc.w += wgt*f.w;
        }
    }
    acc.x = rnd_tf32(acc.x); acc.y = rnd_tf32(acc.y);
    acc.z = rnd_tf32(acc.z); acc.w = rnd_tf32(acc.w);
    ((float4*)(g_A + (size_t)gw*Cn))[lane] = acc;
}

// ---------------- tf32 mma.sync dual GEMM: Y0 = X@W0+b0, Y1 = X@W1 ----------------
// SMEM: sB[256n][128k] swizzled (128KB) | sA 2 stages x [64r][128k] swizzled (64KB) | bias
// Swizzle: addr(row,k) = row*128 + (k ^ ((row&7)<<2))  -> conflict-free frag LDS.
#define TILE_M 64
#define SMEM_FLOATS (32768 + 16384 + 128)

__device__ __forceinline__ void issue_tile(const float* __restrict__ X, int t, int buf,
                                           int tid, uint32_t sA_u) {
    const float* src0 = X + (size_t)t * (TILE_M * 128);
    uint32_t dbase = sA_u + (uint32_t)buf * 32768u;   // bytes
    #pragma unroll
    for (int j = 0; j < 8; j++) {
        int i4 = tid + j*256;            // 0..2047 float4s
        int row = i4 >> 5;
        int kq  = (i4 & 31) << 2;
        uint32_t off = (uint32_t)((row << 7) + (kq ^ ((row & 7) << 2))) * 4u;
        asm volatile("cp.async.cg.shared.global [%0], [%1], 16;"
            :: "r"(dbase + off), "l"(src0 + row*128 + kq));
    }
    asm volatile("cp.async.commit_group;" ::: "memory");
}

__global__ void __launch_bounds__(256, 1)
gemm_dual_mma(const float* __restrict__ X,
              const float* __restrict__ Bt0, const float* __restrict__ Bt1,
              const float* __restrict__ bias,
              float* __restrict__ Y0, float* __restrict__ Y1) {
    extern __shared__ float smf[];
    float* sB    = smf;            // 32768 floats
    float* sA    = smf + 32768;    // 16384 floats (2 stages of 8192)
    float* sbias = smf + 49152;    // 128 floats

    int tid = threadIdx.x;

    // Load both weight matrices (Bt is [n][k]) into swizzled layout: rows 0-127 = W0, 128-255 = W1
    for (int i4 = tid; i4 < 8192; i4 += 256) {
        int n  = i4 >> 5;
        int kq = (i4 & 31) << 2;
        const float* src = (n < 128) ? (Bt0 + n*128 + kq) : (Bt1 + (n-128)*128 + kq);
        float4 v = *(const float4*)src;
        *(float4*)(sB + n*128 + (kq ^ ((n & 7) << 2))) = v;
    }
    if (tid < 128) sbias[tid] = bias[tid];

    uint32_t sA_u = smem_u32(sA);

    int wid = tid >> 5, lane = tid & 31;
    int gidx = lane >> 2, tig = lane & 3;
    int rowg = wid & 1, colg = wid >> 1;       // 2 row groups x 4 col groups
    int m0w = rowg * 32;
    int colbase = colg * 64;                    // 0..255 (128..255 -> Y1)
    const uint32_t xsw = (uint32_t)(gidx << 2); // swizzle xor for this thread's frag rows

    const int ntot = Mn / TILE_M;               // 10000
    const int grid = gridDim.x;

    int t = blockIdx.x;
    if (t < ntot) issue_tile(X, t, 0, tid, sA_u);

    int it = 0;
    for (; t < ntot; t += grid, it++) {
        int tn = t + grid;
        if (tn < ntot) {
            issue_tile(X, tn, (it + 1) & 1, tid, sA_u);
            asm volatile("cp.async.wait_group 1;" ::: "memory");
        } else {
            asm volatile("cp.async.wait_group 0;" ::: "memory");
        }
        __syncthreads();

        const float* sAb = sA + (it & 1) * 8192;

        float c[2][8][4];
        #pragma unroll
        for (int mt = 0; mt < 2; mt++)
            #pragma unroll
            for (int nt = 0; nt < 8; nt++)
                #pragma unroll
                for (int q = 0; q < 4; q++) c[mt][nt][q] = 0.0f;

        #pragma unroll 4
        for (int ks = 0; ks < 16; ks++) {
            int kb = ks * 8;
            uint32_t ka0 = (uint32_t)(kb + tig)     ^ xsw;
            uint32_t ka1 = (uint32_t)(kb + 4 + tig) ^ xsw;

            uint32_t a[2][4];
            #pragma unroll
            for (int mt = 0; mt < 2; mt++) {
                int r0 = m0w + mt*16 + gidx;
                int r1 = r0 + 8;
                a[mt][0] = __float_as_uint(sAb[r0*128 + ka0]);
                a[mt][1] = __float_as_uint(sAb[r1*128 + ka0]);
                a[mt][2] = __float_as_uint(sAb[r0*128 + ka1]);
                a[mt][3] = __float_as_uint(sAb[r1*128 + ka1]);
            }
            uint32_t b[8][2];
            #pragma unroll
            for (int nt = 0; nt < 8; nt++) {
                int n = colbase + nt*8 + gidx;
                b[nt][0] = __float_as_uint(sB[n*128 + ka0]);
                b[nt][1] = __float_as_uint(sB[n*128 + ka1]);
            }
            #pragma unroll
            for (int mt = 0; mt < 2; mt++)
                #pragma unroll
                for (int nt = 0; nt < 8; nt++)
                    mma_tf32(c[mt][nt], a[mt], b[nt]);
        }

        // epilogue
        int rowbase = t * TILE_M + m0w + gidx;
        #pragma unroll
        for (int mt = 0; mt < 2; mt++) {
            int row = rowbase + mt*16;
            #pragma unroll
            for (int nt = 0; nt < 8; nt++) {
                int col = colbase + nt*8 + 2*tig;
                float v0 = c[mt][nt][0], v1 = c[mt][nt][1];
                float v2 = c[mt][nt][2], v3 = c[mt][nt][3];
                if (colg < 2) {
                    float bv0 = sbias[col], bv1 = sbias[col + 1];
                    float2 p01 = make_float2(v0 + bv0, v1 + bv1);
                    float2 p23 = make_float2(v2 + bv0, v3 + bv1);
                    *(float2*)(Y0 + (size_t)row*128 + col)       = p01;
                    *(float2*)(Y0 + (size_t)(row+8)*128 + col)   = p23;
                } else {
                    int c1 = col - 128;
                    *(float2*)(Y1 + (size_t)row*128 + c1)        = make_float2(v0, v1);
                    *(float2*)(Y1 + (size_t)(row+8)*128 + c1)    = make_float2(v2, v3);
                }
            }
        }
        __syncthreads();   // protect sA stage before its next overwrite
    }
}

// ---------------- combine: out = T0 (+Dadd) + sum_{j in N(v)} T1[b,j] ----------------
__global__ void combine_kernel(const float* __restrict__ T0,
                               const float* __restrict__ T1,
                               const float* __restrict__ Dadd,
                               float* __restrict__ outp,
                               int do_round) {
    int gw   = (blockIdx.x*blockDim.x + threadIdx.x) >> 5;
    int lane = threadIdx.x & 31;
    if (gw >= Mn) return;
    int b = gw / Vn;
    int v = gw - b*Vn;

    size_t off = (size_t)gw*Cn + lane*4;
    float4 acc = *(const float4*)(T0 + off);
    if (Dadd) {
        float4 d = *(const float4*)(Dadd + off);
        acc.x += d.x; acc.y += d.y; acc.z += d.z; acc.w += d.w;
    }
    int s = g_rowptr[v];
    int e = g_rowptr[v+1];
    const float* baseT1 = T1 + (size_t)b*Vn*Cn + lane*4;
    for (int p = s; p < e; p++) {
        int j = __ldg(&g_col[p]);
        float4 t = *(const float4*)(baseT1 + (size_t)j*Cn);
        acc.x += t.x; acc.y += t.y; acc.z += t.z; acc.w += t.w;
    }
    if (do_round) {
        acc.x = rnd_tf32(acc.x); acc.y = rnd_tf32(acc.y);
        acc.z = rnd_tf32(acc.z); acc.w = rnd_tf32(acc.w);
    }
    *(float4*)(outp + off) = acc;
}

// ---------------- launch ----------------
extern "C" void kernel_launch(void* const* d_in, const int* in_sizes, int n_in,
                              void* d_out, int out_size) {
    const float* img  = (const float*)d_in[0];
    const float* vpos = (const float*)d_in[1];
    const float* vpad = (const float*)d_in[2];
    const int*   edges= (const int*)  d_in[3];
    const float* w0_1 = (const float*)d_in[4];
    const float* b0_1 = (const float*)d_in[5];
    const float* w1_1 = (const float*)d_in[6];
    const float* w0_2 = (const float*)d_in[7];
    const float* b0_2 = (const float*)d_in[8];
    const float* w1_2 = (const float*)d_in[9];
    const float* w0_3 = (const float*)d_in[10];
    const float* b0_3 = (const float*)d_in[11];
    const float* w1_3 = (const float*)d_in[12];
    float* out = (float*)d_out;

    float *pA, *pD, *pT0, *pT1, *pBt;
    cudaGetSymbolAddress((void**)&pA,  g_A);
    cudaGetSymbolAddress((void**)&pD,  g_Dk);
    cudaGetSymbolAddress((void**)&pT0, g_T0);
    cudaGetSymbolAddress((void**)&pT1, g_T1);
    cudaGetSymbolAddress((void**)&pBt, g_Bt);

    const int smem = SMEM_FLOATS * sizeof(float);   // 197120 B
    cudaFuncSetAttribute(gemm_dual_mma, cudaFuncAttributeMaxDynamicSharedMemorySize, smem);

    int nsm = 148;
    cudaDeviceGetAttribute(&nsm, cudaDevAttrMultiProcessorCount, 0);

    // CSR build
    zero_csr<<<(Vn+255)/256, 256>>>();
    count_edges<<<(En+255)/256, 256>>>(edges);
    scan_kernel<<<1, 1024>>>();
    fill_edges<<<(En+255)/256, 256>>>(edges);

    // weights: transpose + round to tf32
    prep_weights<<<64, 256>>>(w0_1, pBt + 0*16384);
    prep_weights<<<64, 256>>>(w1_1, pBt + 1*16384);
    prep_weights<<<64, 256>>>(w0_2, pBt + 2*16384);
    prep_weights<<<64, 256>>>(w1_2, pBt + 3*16384);
    prep_weights<<<64, 256>>>(w0_3, pBt + 4*16384);
    prep_weights<<<64, 256>>>(w1_3, pBt + 5*16384);

    // vert_align (output tf32-rounded)
    transpose_img<<<dim3((HWn+31)/32, Cn/32, Bn), dim3(32,32)>>>(img);
    vert_align_kernel<<<Mn/8, 256>>>(vpos, vpad);   // g_A = round(G)

    // conv1: D = G@W0+b0 + agg(G@W1)
    gemm_dual_mma<<<nsm, 256, smem>>>(pA, pBt + 0*16384, pBt + 1*16384, b0_1, pT0, pT1);
    combine_kernel<<<Mn/8, 256>>>(pT0, pT1, nullptr, pD, 1);

    // conv2: U = D@W0+b0 + agg(D@W1)
    gemm_dual_mma<<<nsm, 256, smem>>>(pD, pBt + 2*16384, pBt + 3*16384, b0_2, pT0, pT1);
    combine_kernel<<<Mn/8, 256>>>(pT0, pT1, nullptr, pA, 1);

    // conv3 + final residual: out = D + (U@W0+b0 + agg(U@W1))
    gemm_dual_mma<<<nsm, 256, smem>>>(pA, pBt + 4*16384, pBt + 5*16384, b0_3, pT0, pT1);
    combine_kernel<<<Mn/8, 256>>>(pT0, pT1, pD, out, 0);
}